// round 9
// baseline (speedup 1.0000x reference)
#include <cuda_runtime.h>

// Hamilton product of quaternions packed in the last dim (w, x, y, z).
// Shapes: q1, q2: (32, 4096, 64, 4) fp32 -> 8,388,608 quaternions.
//
// FINAL (converged): HBM-bound 2R+1W stream at 6.76 TB/s (85.4% of 8 TB/s
// spec, at the B300 LTS throughput cap). Winning config from the R1-R8
// sweep: 256-bit global ld/st (sm_100+ v8.f32), one LDG.256 per input per
// thread (2 quaternions/thread), .nc loads + .cs stores, TPB=128
// (best occupancy 82% / L1tex-queue balance), branch-free body
// (8,388,608 % 256 == 0).

#define TPB 128
#define QPT 2   // quaternions per thread (one 32B v8 access)

__device__ __forceinline__ void ldg256_nc(const float* p, float4& lo, float4& hi) {
    asm volatile(
        "ld.global.nc.v8.f32 {%0,%1,%2,%3,%4,%5,%6,%7}, [%8];"
        : "=f"(lo.x), "=f"(lo.y), "=f"(lo.z), "=f"(lo.w),
          "=f"(hi.x), "=f"(hi.y), "=f"(hi.z), "=f"(hi.w)
        : "l"(p));
}

__device__ __forceinline__ void stg256_cs(float* p, float4 lo, float4 hi) {
    asm volatile(
        "st.global.cs.v8.f32 [%0], {%1,%2,%3,%4,%5,%6,%7,%8};"
        :: "l"(p),
           "f"(lo.x), "f"(lo.y), "f"(lo.z), "f"(lo.w),
           "f"(hi.x), "f"(hi.y), "f"(hi.z), "f"(hi.w)
        : "memory");
}

__device__ __forceinline__ float4 hprod(float4 a, float4 b) {
    float4 r;
    r.x = a.x * b.x - a.y * b.y - a.z * b.z - a.w * b.w;  // w
    r.y = a.x * b.y + a.y * b.x + a.z * b.w - a.w * b.z;  // x
    r.z = a.x * b.z - a.y * b.w + a.z * b.x + a.w * b.y;  // y
    r.w = a.x * b.w + a.y * b.z - a.z * b.y + a.w * b.x;  // z
    return r;
}

// Branch-free main kernel: grid covers exactly gridDim.x * TPB * 8 floats.
__global__ void __launch_bounds__(TPB) hamilton_kernel(
    const float* __restrict__ q1,
    const float* __restrict__ q2,
    float* __restrict__ out)
{
    // Each thread: 2 adjacent quaternions = 32 bytes; warp covers 1024B contiguous.
    unsigned off = blockIdx.x * (TPB * 8u) + threadIdx.x * 8u;

    float4 a0, a1, b0, b1;
    ldg256_nc(q1 + off, a0, a1);
    ldg256_nc(q2 + off, b0, b1);

    stg256_cs(out + off, hprod(a0, b0), hprod(a1, b1));
}

// Scalar tail for arbitrary n (not hit for this shape: 8,388,608 % 256 == 0).
__global__ void __launch_bounds__(TPB) hamilton_kernel_tail(
    const float4* __restrict__ q1,
    const float4* __restrict__ q2,
    float4* __restrict__ out,
    int start, int n_quat)
{
    int i = start + blockIdx.x * TPB + threadIdx.x;
    if (i < n_quat) out[i] = hprod(q1[i], q2[i]);
}

extern "C" void kernel_launch(void* const* d_in, const int* in_sizes, int n_in,
                              void* d_out, int out_size) {
    const float* q1 = (const float*)d_in[0];
    const float* q2 = (const float*)d_in[1];
    float* out = (float*)d_out;

    int n_quat = in_sizes[0] / 4;          // 8,388,608
    int per_block = TPB * QPT;             // 256 quaternions per block
    int full_blocks = n_quat / per_block;  // 32768 (exact)
    int covered = full_blocks * per_block;

    if (full_blocks > 0)
        hamilton_kernel<<<full_blocks, TPB>>>(q1, q2, out);

    int rem = n_quat - covered;
    if (rem > 0) {
        int tail_blocks = (rem + TPB - 1) / TPB;
        hamilton_kernel_tail<<<tail_blocks, TPB>>>(
            (const float4*)q1, (const float4*)q2, (float4*)out, covered, n_quat);
    }
}

// round 10
// speedup vs baseline: 1.0141x; 1.0141x over previous
#include <cuda_runtime.h>

// Hamilton product of quaternions packed in the last dim (w, x, y, z).
// Shapes: q1, q2: (32, 4096, 64, 4) fp32 -> 8,388,608 quaternions.
// Pure streaming op: float4 per quaternion, 1 thread per quaternion.
//
// R10: exact re-run of the R1 kernel — the configuration that produced the
// best harness bench number (60.29 us) despite the slowest ncu kernel time.
// Discriminates harness-noise (H1) vs config-systematic (H2); see theory.

__global__ void __launch_bounds__(256) hamilton_kernel(
    const float4* __restrict__ q1,
    const float4* __restrict__ q2,
    float4* __restrict__ out,
    int n_quat)
{
    int i = blockIdx.x * blockDim.x + threadIdx.x;
    if (i >= n_quat) return;

    float4 a = q1[i];
    float4 b = q2[i];

    // a = (w1, x1, y1, z1), b = (w2, x2, y2, z2)
    float4 r;
    r.x = a.x * b.x - a.y * b.y - a.z * b.z - a.w * b.w;  // w
    r.y = a.x * b.y + a.y * b.x + a.z * b.w - a.w * b.z;  // x
    r.z = a.x * b.z - a.y * b.w + a.z * b.x + a.w * b.y;  // y
    r.w = a.x * b.w + a.y * b.z - a.z * b.y + a.w * b.x;  // z

    out[i] = r;
}

extern "C" void kernel_launch(void* const* d_in, const int* in_sizes, int n_in,
                              void* d_out, int out_size) {
    const float4* q1 = (const float4*)d_in[0];
    const float4* q2 = (const float4*)d_in[1];
    float4* out = (float4*)d_out;

    int n_quat = in_sizes[0] / 4;  // 8,388,608

    int threads = 256;
    int blocks = (n_quat + threads - 1) / threads;
    hamilton_kernel<<<blocks, threads>>>(q1, q2, out, n_quat);
}